// round 16
// baseline (speedup 1.0000x reference)
#include <cuda_runtime.h>
#include <cuda_fp16.h>
#include <float.h>
#include <stdint.h>

#define NROWS   262144
#define DIM     64
#define NCODES  512
#define NELEM   (NROWS * DIM)
#define TM      128
#define NTILES  (NROWS / TM)     // 2048
#define GRID    152
#define NTHREADS 256

#define RSTRIDE 72               // halves per padded row (144 B: conflict-free ldmatrix)

// SMEM byte offsets
#define SM_AH    0                       // A hi  [128][72] f16  (18432)
#define SM_AM    18432                   // A lo                 (18432)
#define SM_BH    36864                   // B hi  [512][72] f16  (73728)
#define SM_BM    110592                  // B lo                 (73728)
#define SM_NS    184320                  // code norms f32[512]  (2048)
#define SM_RN    186368                  // row norms  f32[128]  (512)
#define SM_REDD  186880                  // f32[128][8]          (4096)
#define SM_REDK  190976                  // int[128][8]          (4096)
#define SM_SIZE  195072

__device__ float g_partials[GRID];
__device__ unsigned int g_done = 0;

__device__ __forceinline__ uint32_t smem_u32(const void* p) {
    uint32_t a;
    asm("{ .reg .u64 t; cvta.to.shared.u64 t, %1; cvt.u32.u64 %0, t; }" : "=r"(a) : "l"(p));
    return a;
}

#define LDSM4(r, addr) \
    asm volatile("ldmatrix.sync.aligned.m8n8.x4.shared.b16 {%0,%1,%2,%3}, [%4];" \
        : "=r"((r)[0]), "=r"((r)[1]), "=r"((r)[2]), "=r"((r)[3]) : "r"(addr))

#define MMA16816(c, a, b0, b1) \
    asm volatile("mma.sync.aligned.m16n8k16.row.col.f32.f16.f16.f32 " \
        "{%0,%1,%2,%3}, {%4,%5,%6,%7}, {%8,%9}, {%0,%1,%2,%3};" \
        : "+f"((c)[0]), "+f"((c)[1]), "+f"((c)[2]), "+f"((c)[3]) \
        : "r"((a)[0]), "r"((a)[1]), "r"((a)[2]), "r"((a)[3]), "r"(b0), "r"(b1))

extern __shared__ char smem_raw[];

__global__ __launch_bounds__(NTHREADS, 1) void vq_kernel(
    const float* __restrict__ x, const float* __restrict__ dict,
    float* __restrict__ out, int out_size)
{
    char* sm = smem_raw;
    const uint32_t smu = smem_u32(sm);

    __half* Bh      = (__half*)(sm + SM_BH);
    __half* Bm      = (__half*)(sm + SM_BM);
    __half* Ah      = (__half*)(sm + SM_AH);
    __half* Am      = (__half*)(sm + SM_AM);
    float*  ns_s    = (float*)(sm + SM_NS);
    float*  rn_s    = (float*)(sm + SM_RN);
    float*  redd    = (float*)(sm + SM_REDD);   // [row][warp]
    int*    redk    = (int*)(sm + SM_REDK);

    const int tid  = threadIdx.x;
    const int w    = tid >> 5;
    const int lane = tid & 31;

    // ---- build codebook splits in SMEM (dict is [D=64][K=512], k fastest) ----
    {
        const float4* d4 = (const float4*)dict;
        for (int i = tid; i < 64 * 128; i += NTHREADS) {
            int d = i >> 7, kq = i & 127;
            float4 v = d4[d * 128 + kq];
            float vv[4] = {v.x, v.y, v.z, v.w};
            #pragma unroll
            for (int j = 0; j < 4; j++) {
                int k = kq * 4 + j;
                __half h = __float2half_rn(vv[j]);
                __half m = __float2half_rn(vv[j] - __half2float(h));
                Bh[k * RSTRIDE + d] = h;
                Bm[k * RSTRIDE + d] = m;
            }
        }
        for (int k = tid; k < NCODES; k += NTHREADS) {
            float s = 0.0f;
            #pragma unroll 8
            for (int d = 0; d < DIM; d++) {
                float v = dict[d * NCODES + k];
                s = fmaf(v, v, s);
            }
            ns_s[k] = s;
        }
    }
    __syncthreads();

    // lane-constant fragment addressing
    const int arow = (lane & 7) + (lane & 8);
    const int bn   = (lane & 7) + ((lane & 16) >> 1);
    const int bk   = (lane & 8);
    const int acol = (lane & 16) ? 8 : 0;
    const int crow = lane >> 2;
    const int ccol = 2 * (lane & 3);

    // ---- B-stationary: each warp owns codes [w*64, w*64+64), fragments in regs ----
    uint32_t BHf[4][4][4];   // [p=16-code tile][kc][frag]
    uint32_t BMf[4][4][4];
    {
        const uint32_t bHbase = smu + SM_BH + (uint32_t)((w * 64 + bn) * RSTRIDE + bk) * 2;
        const uint32_t bMbase = bHbase + (SM_BM - SM_BH);
        #pragma unroll
        for (int p = 0; p < 4; p++)
            #pragma unroll
            for (int kc = 0; kc < 4; kc++) {
                uint32_t o = (uint32_t)(p * 16) * (RSTRIDE * 2) + kc * 32;
                LDSM4(BHf[p][kc], bHbase + o);
                LDSM4(BMf[p][kc], bMbase + o);
            }
    }

    // code-norm pairs for this lane's columns (constant across tiles)
    float nk0_r[8], nk1_r[8];
    #pragma unroll
    for (int nt = 0; nt < 8; nt++) {
        int n = w * 64 + nt * 8 + ccol;
        nk0_r[nt] = ns_s[n];
        nk1_r[nt] = ns_s[n + 1];
    }

    const uint32_t aHbase0 = smu + SM_AH + (uint32_t)(arow * RSTRIDE + acol) * 2;

    const int r2 = tid >> 1;     // row owned for load/merge/gather
    const int ch = tid & 1;      // 32-col half

    float loss_acc = 0.0f;

    #pragma unroll 1
    for (int tile = blockIdx.x; tile < NTILES; tile += GRID) {
        const long row0 = (long)tile * TM;

        // ---- load x tile, split to fp16 hi/lo, row norms ----
        {
            const float4* xr = (const float4*)(x + (row0 + r2) * DIM + ch * 32);
            float rnp = 0.0f;
            #pragma unroll
            for (int j = 0; j < 8; j++) {
                float4 v = xr[j];
                rnp = fmaf(v.x, v.x, rnp); rnp = fmaf(v.y, v.y, rnp);
                rnp = fmaf(v.z, v.z, rnp); rnp = fmaf(v.w, v.w, rnp);
                __half h0 = __float2half_rn(v.x), h1 = __float2half_rn(v.y);
                __half h2 = __float2half_rn(v.z), h3 = __float2half_rn(v.w);
                __half m0 = __float2half_rn(v.x - __half2float(h0));
                __half m1 = __float2half_rn(v.y - __half2float(h1));
                __half m2 = __float2half_rn(v.z - __half2float(h2));
                __half m3 = __float2half_rn(v.w - __half2float(h3));
                int off = r2 * RSTRIDE + ch * 32 + j * 4;
                *(__half2*)(Ah + off)     = __halves2half2(h0, h1);
                *(__half2*)(Ah + off + 2) = __halves2half2(h2, h3);
                *(__half2*)(Am + off)     = __halves2half2(m0, m1);
                *(__half2*)(Am + off + 2) = __halves2half2(m2, m3);
            }
            float rno = __shfl_xor_sync(0xffffffffu, rnp, 1);
            if (ch == 0) rn_s[r2] = rnp + rno;
        }
        // prefetch next tile's x block to L2 (one 128B line per thread)
        if (tile + GRID < NTILES) {
            const float* np = x + ((long)(tile + GRID) * TM + r2) * DIM + ch * 32;
            asm volatile("prefetch.global.L2 [%0];" :: "l"(np));
        }
        __syncthreads();                       // sync1: A/rn ready

        // ---- stream 8 row-tiles of 16 against the warp's resident 64 codes ----
        #pragma unroll 1
        for (int rt = 0; rt < 8; rt++) {
            uint32_t aH[4][4], aM[4][4];
            const uint32_t ab = aHbase0 + (uint32_t)(rt * 16) * (RSTRIDE * 2);
            #pragma unroll
            for (int kc = 0; kc < 4; kc++) {
                LDSM4(aH[kc], ab + kc * 32);
                LDSM4(aM[kc], ab + (SM_AM - SM_AH) + kc * 32);
            }

            float f[8][4];
            #pragma unroll
            for (int nt = 0; nt < 8; nt++)
                #pragma unroll
                for (int q = 0; q < 4; q++) f[nt][q] = 0.0f;

            #pragma unroll
            for (int kc = 0; kc < 4; kc++) {
                #pragma unroll
                for (int nt = 0; nt < 8; nt++)
                    MMA16816(f[nt], aH[kc], BHf[nt >> 1][kc][(nt & 1) * 2], BHf[nt >> 1][kc][(nt & 1) * 2 + 1]);
                #pragma unroll
                for (int nt = 0; nt < 8; nt++)
                    MMA16816(f[nt], aM[kc], BHf[nt >> 1][kc][(nt & 1) * 2], BHf[nt >> 1][kc][(nt & 1) * 2 + 1]);
                #pragma unroll
                for (int nt = 0; nt < 8; nt++)
                    MMA16816(f[nt], aH[kc], BMf[nt >> 1][kc][(nt & 1) * 2], BMf[nt >> 1][kc][(nt & 1) * 2 + 1]);
            }

            // ---- epilogue: same formula, tree-reduced (exact same min / tie rule) ----
            const float rn0 = rn_s[rt * 16 + crow];
            const float rn1 = rn_s[rt * 16 + 8 + crow];
            float dv0[16], dv1[16];
            #pragma unroll
            for (int nt = 0; nt < 8; nt++) {
                dv0[nt * 2]     = fmaf(-2.0f, f[nt][0], rn0 + nk0_r[nt]);
                dv0[nt * 2 + 1] = fmaf(-2.0f, f[nt][1], rn0 + nk1_r[nt]);
                dv1[nt * 2]     = fmaf(-2.0f, f[nt][2], rn1 + nk0_r[nt]);
                dv1[nt * 2 + 1] = fmaf(-2.0f, f[nt][3], rn1 + nk1_r[nt]);
            }
            // value min (tree)
            float t0[8], t1[8];
            #pragma unroll
            for (int i = 0; i < 8; i++) {
                t0[i] = fminf(dv0[2 * i], dv0[2 * i + 1]);
                t1[i] = fminf(dv1[2 * i], dv1[2 * i + 1]);
            }
            #pragma unroll
            for (int i = 0; i < 4; i++) {
                t0[i] = fminf(t0[i], t0[i + 4]);
                t1[i] = fminf(t1[i], t1[i + 4]);
            }
            float best0 = fminf(fminf(t0[0], t0[2]), fminf(t0[1], t0[3]));
            float best1 = fminf(fminf(t1[0], t1[2]), fminf(t1[1], t1[3]));
            best0 = fminf(best0, __shfl_xor_sync(0xffffffffu, best0, 1));
            best0 = fminf(best0, __shfl_xor_sync(0xffffffffu, best0, 2));
            best1 = fminf(best1, __shfl_xor_sync(0xffffffffu, best1, 1));
            best1 = fminf(best1, __shfl_xor_sync(0xffffffffu, best1, 2));
            // lowest k matching the min (descending scan -> lowest local k wins)
            int bk0 = 0x7FFFFFFF, bk1 = 0x7FFFFFFF;
            #pragma unroll
            for (int nt = 7; nt >= 0; nt--) {
                int n = w * 64 + nt * 8 + ccol;
                if (dv0[nt * 2 + 1] == best0) bk0 = n + 1;
                if (dv0[nt * 2]     == best0) bk0 = n;
                if (dv1[nt * 2 + 1] == best1) bk1 = n + 1;
                if (dv1[nt * 2]     == best1) bk1 = n;
            }
            bk0 = min(bk0, __shfl_xor_sync(0xffffffffu, bk0, 1));
            bk0 = min(bk0, __shfl_xor_sync(0xffffffffu, bk0, 2));
            bk1 = min(bk1, __shfl_xor_sync(0xffffffffu, bk1, 1));
            bk1 = min(bk1, __shfl_xor_sync(0xffffffffu, bk1, 2));

            if ((lane & 3) == 0) {
                int row_a = rt * 16 + crow;
                redd[row_a * 8 + w] = best0;  redk[row_a * 8 + w] = bk0;
                redd[(row_a + 8) * 8 + w] = best1;  redk[(row_a + 8) * 8 + w] = bk1;
            }
        }
        __syncthreads();                       // sync2: redd/redk ready; A reads done

        // ---- per-pair redundant merge (no 3rd barrier) + gather ----
        {
            float bd = redd[r2 * 8];
            int   bkk = redk[r2 * 8];
            #pragma unroll
            for (int j = 1; j < 8; j++) {
                float dv = redd[r2 * 8 + j];
                int   kk = redk[r2 * 8 + j];
                if (dv < bd || (dv == bd && kk < bkk)) { bd = dv; bkk = kk; }
            }
            if (ch == 0) loss_acc += bd;       // ||x - q||^2, once per row

            float4* dst = (float4*)(out + (row0 + r2) * DIM + ch * 32);
            #pragma unroll
            for (int j = 0; j < 8; j++) {
                int d0 = bkk * RSTRIDE + ch * 32 + j * 4;
                __half2 ha = *(const __half2*)(Bh + d0);
                __half2 hb = *(const __half2*)(Bh + d0 + 2);
                __half2 ma = *(const __half2*)(Bm + d0);
                __half2 mb = *(const __half2*)(Bm + d0 + 2);
                float2 fa = __half22float2(ha), fb = __half22float2(hb);
                float2 ga = __half22float2(ma), gb = __half22float2(mb);
                float4 o;
                o.x = fa.x + ga.x; o.y = fa.y + ga.y;
                o.z = fb.x + gb.x; o.w = fb.y + gb.y;
                dst[j] = o;
            }
        }
        // hazards: redd re-written only after next sync1; Ah/Am re-written in next
        // load phase, whose MMA reads were fenced by sync2 above.
    }

    // ---- per-CTA loss reduction (deterministic) ----
    __syncthreads();
    float v = loss_acc;
    #pragma unroll
    for (int o = 16; o > 0; o >>= 1) v += __shfl_down_sync(0xffffffffu, v, o);
    if (lane == 0) rn_s[w] = v;
    __syncthreads();
    if (tid == 0) {
        float t = 0.0f;
        #pragma unroll
        for (int i = 0; i < 8; i++) t += rn_s[i];
        g_partials[blockIdx.x] = t;
        __threadfence();
        unsigned int old = atomicAdd(&g_done, 1u);
        if (old == GRID - 1) {
            g_done = 0;                      // reset for next graph replay
            float s = 0.0f;
            #pragma unroll 8
            for (int i = 0; i < GRID; i++) s += g_partials[i];
            float m = s / (float)NELEM;
            if (out_size > NELEM) out[NELEM] = m + 0.25f * m;
        }
    }
}

extern "C" void kernel_launch(void* const* d_in, const int* in_sizes, int n_in,
                              void* d_out, int out_size) {
    const float* x    = (const float*)d_in[0];   // [16,128,128,64]
    const float* dict = (const float*)d_in[1];   // [64,512]
    float* out = (float*)d_out;

    cudaFuncSetAttribute(vq_kernel, cudaFuncAttributeMaxDynamicSharedMemorySize, SM_SIZE);
    vq_kernel<<<GRID, NTHREADS, SM_SIZE>>>(x, dict, out, out_size);
}

// round 17
// speedup vs baseline: 1.6011x; 1.6011x over previous
#include <cuda_runtime.h>
#include <cuda_fp16.h>
#include <float.h>
#include <stdint.h>

#define NROWS   262144
#define DIM     64
#define NCODES  512
#define NELEM   (NROWS * DIM)
#define TM      128
#define NTILES  (NROWS / TM)     // 2048
#define GRID    152
#define NTHREADS 256

#define RSTRIDE 72               // halves per padded row (144 B: conflict-free ldmatrix)

// SMEM byte offsets
#define SM_AH    0                       // A hi  [128][72] f16  (18432)
#define SM_AM    18432                   // A lo                 (18432)
#define SM_BH    36864                   // B hi  [512][72] f16  (73728)
#define SM_BM    110592                  // B lo                 (73728)
#define SM_NS    184320                  // code norms f32[512]  (2048)
#define SM_RN    186368                  // row norms  f32[128]  (512)
#define SM_REDD  186880                  // f32[128][8]          (4096)
#define SM_REDK  190976                  // int[128][8]          (4096)
#define SM_SIZE  195072

__device__ float g_partials[GRID];
__device__ unsigned int g_done = 0;

__device__ __forceinline__ uint32_t smem_u32(const void* p) {
    uint32_t a;
    asm("{ .reg .u64 t; cvta.to.shared.u64 t, %1; cvt.u32.u64 %0, t; }" : "=r"(a) : "l"(p));
    return a;
}

#define LDSM4(r, addr) \
    asm volatile("ldmatrix.sync.aligned.m8n8.x4.shared.b16 {%0,%1,%2,%3}, [%4];" \
        : "=r"((r)[0]), "=r"((r)[1]), "=r"((r)[2]), "=r"((r)[3]) : "r"(addr))

#define MMA16816(c, a, b0, b1) \
    asm volatile("mma.sync.aligned.m16n8k16.row.col.f32.f16.f16.f32 " \
        "{%0,%1,%2,%3}, {%4,%5,%6,%7}, {%8,%9}, {%0,%1,%2,%3};" \
        : "+f"((c)[0]), "+f"((c)[1]), "+f"((c)[2]), "+f"((c)[3]) \
        : "r"((a)[0]), "r"((a)[1]), "r"((a)[2]), "r"((a)[3]), "r"(b0), "r"(b1))

extern __shared__ char smem_raw[];

__global__ __launch_bounds__(NTHREADS, 1) void vq_kernel(
    const float* __restrict__ x, const float* __restrict__ dict,
    float* __restrict__ out, int out_size)
{
    char* sm = smem_raw;
    const uint32_t smu = smem_u32(sm);

    __half* Bh      = (__half*)(sm + SM_BH);
    __half* Bm      = (__half*)(sm + SM_BM);
    __half* Ah      = (__half*)(sm + SM_AH);
    __half* Am      = (__half*)(sm + SM_AM);
    float*  ns_s    = (float*)(sm + SM_NS);
    float*  rn_s    = (float*)(sm + SM_RN);
    float*  redd    = (float*)(sm + SM_REDD);   // [row][warp]
    int*    redk    = (int*)(sm + SM_REDK);

    const int tid  = threadIdx.x;
    const int w    = tid >> 5;
    const int lane = tid & 31;

    // ---- build codebook splits in SMEM (dict is [D=64][K=512], k fastest) ----
    {
        const float4* d4 = (const float4*)dict;
        for (int i = tid; i < 64 * 128; i += NTHREADS) {
            int d = i >> 7, kq = i & 127;
            float4 v = d4[d * 128 + kq];
            float vv[4] = {v.x, v.y, v.z, v.w};
            #pragma unroll
            for (int j = 0; j < 4; j++) {
                int k = kq * 4 + j;
                __half h = __float2half_rn(vv[j]);
                __half m = __float2half_rn(vv[j] - __half2float(h));
                Bh[k * RSTRIDE + d] = h;
                Bm[k * RSTRIDE + d] = m;
            }
        }
        for (int k = tid; k < NCODES; k += NTHREADS) {
            float s = 0.0f;
            #pragma unroll 8
            for (int d = 0; d < DIM; d++) {
                float v = dict[d * NCODES + k];
                s = fmaf(v, v, s);
            }
            ns_s[k] = s;
        }
    }
    __syncthreads();

    // lane-constant fragment addressing
    const int arow = (lane & 7) + (lane & 8);
    const int bn   = (lane & 7) + ((lane & 16) >> 1);
    const int bk   = (lane & 8);
    const int acol = (lane & 16) ? 8 : 0;
    const int crow = lane >> 2;
    const int ccol = 2 * (lane & 3);

    // ---- B-stationary: each warp owns codes [w*64, w*64+64), fragments in regs ----
    uint32_t BHf[4][4][4];   // [p=16-code tile][kc][frag]
    uint32_t BMf[4][4][4];
    {
        const uint32_t bHbase = smu + SM_BH + (uint32_t)((w * 64 + bn) * RSTRIDE + bk) * 2;
        const uint32_t bMbase = bHbase + (SM_BM - SM_BH);
        #pragma unroll
        for (int p = 0; p < 4; p++)
            #pragma unroll
            for (int kc = 0; kc < 4; kc++) {
                uint32_t o = (uint32_t)(p * 16) * (RSTRIDE * 2) + kc * 32;
                LDSM4(BHf[p][kc], bHbase + o);
                LDSM4(BMf[p][kc], bMbase + o);
            }
    }

    // code-norm pairs for this lane's columns (constant across tiles)
    float nk0_r[8], nk1_r[8];
    #pragma unroll
    for (int nt = 0; nt < 8; nt++) {
        int n = w * 64 + nt * 8 + ccol;
        nk0_r[nt] = ns_s[n];
        nk1_r[nt] = ns_s[n + 1];
    }

    const uint32_t aHbase0 = smu + SM_AH + (uint32_t)(arow * RSTRIDE + acol) * 2;

    const int r2 = tid >> 1;     // row owned for load/merge/gather
    const int ch = tid & 1;      // 32-col half

    float loss_acc = 0.0f;

    #pragma unroll 1
    for (int tile = blockIdx.x; tile < NTILES; tile += GRID) {
        const long row0 = (long)tile * TM;

        // ---- load x tile, split to fp16 hi/lo, row norms ----
        {
            const float4* xr = (const float4*)(x + (row0 + r2) * DIM + ch * 32);
            float rnp = 0.0f;
            #pragma unroll
            for (int j = 0; j < 8; j++) {
                float4 v = xr[j];
                rnp = fmaf(v.x, v.x, rnp); rnp = fmaf(v.y, v.y, rnp);
                rnp = fmaf(v.z, v.z, rnp); rnp = fmaf(v.w, v.w, rnp);
                __half h0 = __float2half_rn(v.x), h1 = __float2half_rn(v.y);
                __half h2 = __float2half_rn(v.z), h3 = __float2half_rn(v.w);
                __half m0 = __float2half_rn(v.x - __half2float(h0));
                __half m1 = __float2half_rn(v.y - __half2float(h1));
                __half m2 = __float2half_rn(v.z - __half2float(h2));
                __half m3 = __float2half_rn(v.w - __half2float(h3));
                int off = r2 * RSTRIDE + ch * 32 + j * 4;
                *(__half2*)(Ah + off)     = __halves2half2(h0, h1);
                *(__half2*)(Ah + off + 2) = __halves2half2(h2, h3);
                *(__half2*)(Am + off)     = __halves2half2(m0, m1);
                *(__half2*)(Am + off + 2) = __halves2half2(m2, m3);
            }
            float rno = __shfl_xor_sync(0xffffffffu, rnp, 1);
            if (ch == 0) rn_s[r2] = rnp + rno;
        }
        // prefetch next tile's x block to L2 (one 128B line per thread)
        if (tile + GRID < NTILES) {
            const float* np = x + ((long)(tile + GRID) * TM + r2) * DIM + ch * 32;
            asm volatile("prefetch.global.L2 [%0];" :: "l"(np));
        }
        __syncthreads();                       // sync1: A/rn ready, redd free

        // ---- stream 8 row-tiles of 16 against the warp's resident 64 codes ----
        #pragma unroll 1
        for (int rt = 0; rt < 8; rt++) {
            uint32_t aH[4][4], aM[4][4];
            const uint32_t ab = aHbase0 + (uint32_t)(rt * 16) * (RSTRIDE * 2);
            #pragma unroll
            for (int kc = 0; kc < 4; kc++) {
                LDSM4(aH[kc], ab + kc * 32);
                LDSM4(aM[kc], ab + (SM_AM - SM_AH) + kc * 32);
            }

            float f[8][4];
            #pragma unroll
            for (int nt = 0; nt < 8; nt++)
                #pragma unroll
                for (int q = 0; q < 4; q++) f[nt][q] = 0.0f;

            #pragma unroll
            for (int kc = 0; kc < 4; kc++) {
                #pragma unroll
                for (int nt = 0; nt < 8; nt++)
                    MMA16816(f[nt], aH[kc], BHf[nt >> 1][kc][(nt & 1) * 2], BHf[nt >> 1][kc][(nt & 1) * 2 + 1]);
                #pragma unroll
                for (int nt = 0; nt < 8; nt++)
                    MMA16816(f[nt], aM[kc], BHf[nt >> 1][kc][(nt & 1) * 2], BHf[nt >> 1][kc][(nt & 1) * 2 + 1]);
                #pragma unroll
                for (int nt = 0; nt < 8; nt++)
                    MMA16816(f[nt], aH[kc], BMf[nt >> 1][kc][(nt & 1) * 2], BMf[nt >> 1][kc][(nt & 1) * 2 + 1]);
            }

            const float rn0 = rn_s[rt * 16 + crow];
            const float rn1 = rn_s[rt * 16 + 8 + crow];
            float best0 = FLT_MAX, best1 = FLT_MAX;
            int   bk0 = 0, bk1 = 0;

            #pragma unroll
            for (int nt = 0; nt < 8; nt++) {
                int n = w * 64 + nt * 8 + ccol;
                float d00 = fmaf(-2.0f, f[nt][0], rn0 + nk0_r[nt]);
                float d01 = fmaf(-2.0f, f[nt][1], rn0 + nk1_r[nt]);
                float d10 = fmaf(-2.0f, f[nt][2], rn1 + nk0_r[nt]);
                float d11 = fmaf(-2.0f, f[nt][3], rn1 + nk1_r[nt]);
                if (d00 < best0) { best0 = d00; bk0 = n; }
                if (d01 < best0) { best0 = d01; bk0 = n + 1; }
                if (d10 < best1) { best1 = d10; bk1 = n; }
                if (d11 < best1) { best1 = d11; bk1 = n + 1; }
            }

            // merge over lane bits 0-1 (interleaved code cols)
            #pragma unroll
            for (int off = 1; off <= 2; off <<= 1) {
                float od0 = __shfl_xor_sync(0xffffffffu, best0, off);
                int   ok0 = __shfl_xor_sync(0xffffffffu, bk0, off);
                if (od0 < best0 || (od0 == best0 && ok0 < bk0)) { best0 = od0; bk0 = ok0; }
                float od1 = __shfl_xor_sync(0xffffffffu, best1, off);
                int   ok1 = __shfl_xor_sync(0xffffffffu, bk1, off);
                if (od1 < best1 || (od1 == best1 && ok1 < bk1)) { best1 = od1; bk1 = ok1; }
            }
            if ((lane & 3) == 0) {
                int row_a = rt * 16 + crow;
                redd[row_a * 8 + w] = best0;  redk[row_a * 8 + w] = bk0;
                redd[(row_a + 8) * 8 + w] = best1;  redk[(row_a + 8) * 8 + w] = bk1;
            }
        }
        __syncthreads();                       // sync2: redd/redk ready; A reads done

        // ---- per-pair redundant merge (identical compare chain -> same bits) ----
        {
            float bd = redd[r2 * 8];
            int   bkk = redk[r2 * 8];
            #pragma unroll
            for (int j = 1; j < 8; j++) {
                float dv = redd[r2 * 8 + j];
                int   kk = redk[r2 * 8 + j];
                if (dv < bd || (dv == bd && kk < bkk)) { bd = dv; bkk = kk; }
            }
            if (ch == 0) loss_acc += bd;       // ||x - q||^2, once per row

            // gather output: q = h + m (reconstructed codeword)
            float4* dst = (float4*)(out + (row0 + r2) * DIM + ch * 32);
            #pragma unroll
            for (int j = 0; j < 8; j++) {
                int d0 = bkk * RSTRIDE + ch * 32 + j * 4;
                __half2 ha = *(const __half2*)(Bh + d0);
                __half2 hb = *(const __half2*)(Bh + d0 + 2);
                __half2 ma = *(const __half2*)(Bm + d0);
                __half2 mb = *(const __half2*)(Bm + d0 + 2);
                float2 fa = __half22float2(ha), fb = __half22float2(hb);
                float2 ga = __half22float2(ma), gb = __half22float2(mb);
                float4 o;
                o.x = fa.x + ga.x; o.y = fa.y + ga.y;
                o.z = fb.x + gb.x; o.w = fb.y + gb.y;
                dst[j] = o;
            }
        }
        // hazards: redd/redk rewritten only after next sync1; next load phase
        // writes Ah/Am (MMA reads fenced by sync2) and rn_s (not read here).
    }

    // ---- per-CTA loss reduction (deterministic) ----
    __syncthreads();
    float v = loss_acc;
    #pragma unroll
    for (int o = 16; o > 0; o >>= 1) v += __shfl_down_sync(0xffffffffu, v, o);
    if (lane == 0) rn_s[w] = v;
    __syncthreads();
    if (tid == 0) {
        float t = 0.0f;
        #pragma unroll
        for (int i = 0; i < 8; i++) t += rn_s[i];
        g_partials[blockIdx.x] = t;
        __threadfence();
        unsigned int old = atomicAdd(&g_done, 1u);
        if (old == GRID - 1) {
            g_done = 0;                      // reset for next graph replay
            float s = 0.0f;
            #pragma unroll 8
            for (int i = 0; i < GRID; i++) s += g_partials[i];
            float m = s / (float)NELEM;
            if (out_size > NELEM) out[NELEM] = m + 0.25f * m;
        }
    }
}

extern "C" void kernel_launch(void* const* d_in, const int* in_sizes, int n_in,
                              void* d_out, int out_size) {
    const float* x    = (const float*)d_in[0];   // [16,128,128,64]
    const float* dict = (const float*)d_in[1];   // [64,512]
    float* out = (float*)d_out;

    cudaFuncSetAttribute(vq_kernel, cudaFuncAttributeMaxDynamicSharedMemorySize, SM_SIZE);
    vq_kernel<<<GRID, NTHREADS, SM_SIZE>>>(x, dict, out, out_size);
}